// round 7
// baseline (speedup 1.0000x reference)
#include <cuda_runtime.h>
#include <cuda_fp16.h>

// out[b,c,h,w] = (Re + Im)( FFT4D(x) ) / 2^26 ; x: [16,64,256,256] f32.
//
// Pipeline:
//  p12: x -> B[ns][bc][w']   (fused: real 256-pt W-FFT (two-for-one) +
//        256-pt H-FFT, all inside one 130KB smem tile per bc;
//        B row index ns = FFT position, true h = brev8(ns); half2 packed)
//  p3 : B -> out             (16-pt B-FFT + 64-pt C-FFT + Hermitian-mirror
//                             output, fused; w' 0..127)
//  p3e: w'=128 plane -> out column w=128
#define W2 132
__device__ unsigned int g_B[34603008];   // 1024*256*132 half2

#define INV_N (1.0f / 67108864.0f)
#define PI_F 3.14159265358979f

__device__ __forceinline__ float2 cmul(float2 a, float2 b) {
    return make_float2(a.x*b.x - a.y*b.y, a.x*b.y + a.y*b.x);
}
__device__ __forceinline__ float2 cadd(float2 a, float2 b) { return make_float2(a.x+b.x, a.y+b.y); }
__device__ __forceinline__ float2 csub(float2 a, float2 b) { return make_float2(a.x-b.x, a.y-b.y); }
__device__ __forceinline__ float2 Wang(float e, float sc) {   // exp(-i*pi*e*sc), MUFU
    float2 w; __sincosf(-e * sc * PI_F, &w.y, &w.x); return w;
}
__device__ __forceinline__ unsigned int pk(float2 v) {
    __half2 h = __floats2half2_rn(v.x, v.y);
    return *reinterpret_cast<unsigned int*>(&h);
}
__device__ __forceinline__ float2 upk(unsigned int u) {
    __half2 h = *reinterpret_cast<__half2*>(&u);
    return __half22float2(h);
}
__device__ __forceinline__ int brev4(int v) { return (int)(__brev((unsigned)v) >> 28); }
__device__ __forceinline__ int brev6(int v) { return (int)(__brev((unsigned)v) >> 26); }
__device__ __forceinline__ int brev8(int v) { return (int)(__brev((unsigned)v) >> 24); }

// W16^e, e = 0..7 (compile-time constants)
__device__ __constant__ float2 T16C[8] = {
    { 1.00000000f,  0.00000000f}, { 0.92387953f, -0.38268343f},
    { 0.70710678f, -0.70710678f}, { 0.38268343f, -0.92387953f},
    { 0.00000000f, -1.00000000f}, {-0.38268343f, -0.92387953f},
    {-0.70710678f, -0.70710678f}, {-0.92387953f, -0.38268343f}};

// ---------------------------------------------------------------------------
// Warp-resident 256-pt DIF FFT. Input z[i] = x[lane + 32*i] natural order.
// Output: position n = lane + 32*i holds X[brev8(n)].
// ---------------------------------------------------------------------------
__device__ __forceinline__ void fft256_warp(float2 z[8], int lane) {
    const float sc = 1.0f / 128.0f;
#pragma unroll
    for (int i = 0; i < 4; i++) {                       // h = 128
        float2 a = z[i], b = z[i+4];
        z[i]   = cadd(a, b);
        z[i+4] = cmul(Wang((float)(lane + 32*i), sc), csub(a, b));
    }
    {                                                   // h = 64
        float2 w0 = Wang((float)(2*lane), sc);
        float2 w1 = Wang((float)(2*lane + 64), sc);
        float2 a, b;
        a = z[0]; b = z[2]; z[0] = cadd(a,b); z[2] = cmul(w0, csub(a,b));
        a = z[1]; b = z[3]; z[1] = cadd(a,b); z[3] = cmul(w1, csub(a,b));
        a = z[4]; b = z[6]; z[4] = cadd(a,b); z[6] = cmul(w0, csub(a,b));
        a = z[5]; b = z[7]; z[5] = cadd(a,b); z[7] = cmul(w1, csub(a,b));
    }
    {                                                   // h = 32
        float2 w = Wang((float)(4*lane), sc);
#pragma unroll
        for (int i = 0; i < 8; i += 2) {
            float2 a = z[i], b = z[i+1];
            z[i]   = cadd(a, b);
            z[i+1] = cmul(w, csub(a, b));
        }
    }
#pragma unroll
    for (int m = 16; m >= 1; m >>= 1) {                 // cross-lane stages
        float2 w = Wang((float)((lane & (m-1)) * (128/m)), sc);
        bool hi = (lane & m) != 0;
#pragma unroll
        for (int i = 0; i < 8; i++) {
            float2 o;
            o.x = __shfl_xor_sync(0xffffffffu, z[i].x, m);
            o.y = __shfl_xor_sync(0xffffffffu, z[i].y, m);
            if (hi) z[i] = cmul(w, csub(o, z[i]));
            else    z[i] = cadd(z[i], o);
        }
    }
}

// 16-pt DIF; position p holds spectrum index brev4(p).
__device__ __forceinline__ void dif16(float2 r[16]) {
#pragma unroll
    for (int h = 8; h >= 1; h >>= 1) {
#pragma unroll
        for (int base = 0; base < 16; base += 2*h) {
#pragma unroll
            for (int j = 0; j < h; j++) {
                float2 a = r[base+j], b = r[base+j+h];
                r[base+j]   = cadd(a, b);
                r[base+j+h] = cmul(T16C[j * (8/h)], csub(a, b));
            }
        }
    }
}

// ---------------------------------------------------------------------------
// p12: fused W-FFT + H-FFT for one bc plane. 1024 threads, smem tile
// T[128 pair-rows][259] packed half2 (129.5 KB).
//  W-phase: pair p = rows (2p, 2p+1) packed as re/im; warp FFT; store packed
//           spectrum Z at column n = FFT position (scrambled), row p.
//  H-phase: task w' (0..128): q1 = brev8(w'), q2 = brev8((256-w')&255).
//           Load Z1/Z2 from cols q1/q2, Hermitian-unpack even/odd h in regs,
//           warp FFT over h, write back in place (cols q1 / q2; w'=0 high
//           half -> col 256, w'=128 high half -> col 257). Tasks own disjoint
//           column pairs -> no barrier inside the phase.
//  Store:   B[ns][bc][w'] coalesced (512B rows); value(ns,w') from
//           col q1 (ns<128) or q2-special (ns>=128).
// ---------------------------------------------------------------------------
#define TP 259
__global__ void __launch_bounds__(1024) p12_kernel(const float* __restrict__ x) {
    extern __shared__ unsigned int T[];   // [128][TP]
    int tid  = threadIdx.x;
    int lane = tid & 31, wp = tid >> 5;   // 32 warps
    int bc = blockIdx.x;

    // W-phase: 128 two-for-one FFTs.
#pragma unroll
    for (int it = 0; it < 4; it++) {
        int p = wp + 32*it;
        const float* r0 = x + ((size_t)bc * 256 + 2*p) * 256;
        float2 z[8];
#pragma unroll
        for (int i = 0; i < 8; i++) {
            int n = lane + 32*i;
            z[i] = make_float2(r0[n], r0[256 + n]);
        }
        fft256_warp(z, lane);
#pragma unroll
        for (int i = 0; i < 8; i++)
            T[p * TP + lane + 32*i] = pk(z[i]);
    }
    __syncthreads();

    // H-phase: 129 column tasks over 32 warps (warp 0 takes task 128).
    for (int it = 0; it < 5; it++) {
        int wq = wp + 32*it;
        if (wq > 128) break;
        int q1 = brev8(wq);
        int q2 = (wq == 0) ? 0 : brev8(256 - wq);
        float2 z[8];
#pragma unroll
        for (int i = 0; i < 8; i++) {
            int h  = lane + 32*i;
            int pr = h >> 1;
            float2 Z1 = upk(T[pr * TP + q1]);
            float2 Z2 = upk(T[pr * TP + q2]);
            if (h & 1) z[i] = make_float2(0.5f*(Z1.y + Z2.y), 0.5f*(Z2.x - Z1.x));
            else       z[i] = make_float2(0.5f*(Z1.x + Z2.x), 0.5f*(Z1.y - Z2.y));
        }
        fft256_warp(z, lane);
        int cq2 = (wq == 0) ? 256 : (wq == 128 ? 257 : q2);
#pragma unroll
        for (int i = 0; i < 4; i++)
            T[(lane + 32*i) * TP + q1] = pk(z[i]);
#pragma unroll
        for (int i = 4; i < 8; i++)
            T[(lane + 32*(i-4)) * TP + cq2] = pk(z[i]);
    }
    __syncthreads();

    // Store phase: 8 groups of 128 threads; group g handles rows ns = g+8j.
    int wq = tid & 127;
    int g  = tid >> 7;
    int q1  = brev8(wq);
    int q2s = (wq == 0) ? 256 : brev8(256 - wq);
    unsigned int* dB = g_B + bc * (size_t)W2;
#pragma unroll
    for (int j = 0; j < 32; j++) {
        int ns = g + 8*j;
        unsigned int v = (ns < 128) ? T[ns * TP + q1]
                                    : T[(ns - 128) * TP + q2s];
        dB[(size_t)ns * 1024 * W2 + wq] = v;
        if (wq == 0) {   // w'=128 column (cols 1 / 257 per H-phase mapping)
            unsigned int v2 = (ns < 128) ? T[ns * TP + 1]
                                         : T[(ns - 128) * TP + 257];
            dB[(size_t)ns * 1024 * W2 + 128] = v2;
        }
    }
}

// ---------------------------------------------------------------------------
// p3: FUSED (B,C)-FFT + output, w' 0..127. Block = (stored h, 8-w'-chunk).
// 512 threads, 74 KB smem tile S[1024 bc][9] -> 2 CTAs/SM.
// ---------------------------------------------------------------------------
#define SR 9
__global__ void __launch_bounds__(512) p3_kernel(float* __restrict__ out) {
    extern __shared__ float2 S[];   // [1024][SR]
    int tid = threadIdx.x;
    int ch = blockIdx.x & 15;
    int hs = blockIdx.x >> 4;
    int w0 = ch << 3;
    int w  = tid & 7;
    int c  = tid >> 3;              // 0..63

    // Phase A: 16-pt b-FFT straight from global (coalesced reads).
    {
        const unsigned int* Bb = g_B + (size_t)hs * 1024 * W2 + w0 + w;
        float2 r[16];
#pragma unroll
        for (int b = 0; b < 16; b++) r[b] = upk(Bb[(size_t)(b*64 + c) * W2]);
        dif16(r);
#pragma unroll
        for (int p = 0; p < 16; p++) S[(p*64 + c)*SR + w] = r[p];
    }
    __syncthreads();

    // Phase B: 64-pt c-FFT; warp p owns rows [p*64, p*64+64), cols w0..w0+7.
    int lane = tid & 31;
    int p    = tid >> 5;            // 0..15
    const float sc = 1.0f / 32.0f;
    float2 tw32 = Wang((float)lane, sc);
#pragma unroll
    for (int wg = 0; wg < 2; wg++) {
        float2 z0[4], z1[4];
#pragma unroll
        for (int k = 0; k < 4; k++) {
            z0[k] = S[(p*64 + lane)*SR      + wg*4 + k];
            z1[k] = S[(p*64 + lane + 32)*SR + wg*4 + k];
        }
#pragma unroll
        for (int k = 0; k < 4; k++) {   // h = 32 register stage
            float2 a = z0[k], b = z1[k];
            z0[k] = cadd(a, b);
            z1[k] = cmul(tw32, csub(a, b));
        }
#pragma unroll
        for (int m = 16; m >= 1; m >>= 1) {
            float2 tw = Wang((float)((lane & (m-1)) * (32/m)), sc);
            bool hi = (lane & m) != 0;
#pragma unroll
            for (int k = 0; k < 4; k++) {
                float2 o;
                o.x = __shfl_xor_sync(0xffffffffu, z0[k].x, m);
                o.y = __shfl_xor_sync(0xffffffffu, z0[k].y, m);
                z0[k] = hi ? cmul(tw, csub(o, z0[k])) : cadd(z0[k], o);
                o.x = __shfl_xor_sync(0xffffffffu, z1[k].x, m);
                o.y = __shfl_xor_sync(0xffffffffu, z1[k].y, m);
                z1[k] = hi ? cmul(tw, csub(o, z1[k])) : cadd(z1[k], o);
            }
        }
#pragma unroll
        for (int k = 0; k < 4; k++) {
            S[(p*64 + lane)*SR      + wg*4 + k] = z0[k];
            S[(p*64 + lane + 32)*SR + wg*4 + k] = z1[k];
        }
    }
    __syncthreads();

    // Phase C: output. row = c + 64*j -> b = brev4(j), true c = brev6(c).
    int h  = brev8(hs);
    int hm = (256 - h) & 255;
    int wv = w0 + w;
    int ct = brev6(c);
#pragma unroll
    for (int j = 0; j < 16; j++) {
        int row = c + 64*j;
        int b = brev4(j);
        float2 v = S[row*SR + w];
        out[((size_t)((b << 6) | ct) * 256 + h) * 256 + wv] = (v.x + v.y) * INV_N;
        if (wv >= 1) {
            int bcm = (((16 - b) & 15) << 6) | ((64 - ct) & 63);
            out[((size_t)bcm * 256 + hm) * 256 + (256 - wv)] = (v.x - v.y) * INV_N;
        }
    }
}

// p3e: (B,C)-FFT + output for the w'=128 plane (self-mirror column).
__global__ void __launch_bounds__(128) p3e_kernel(float* __restrict__ out) {
    __shared__ float2 S[1024];
    int tid = threadIdx.x;
    int hs = blockIdx.x;

    for (int idx = tid; idx < 1024; idx += 128)
        S[idx] = upk(g_B[((size_t)hs * 1024 + idx) * W2 + 128]);
    __syncthreads();

    if (tid < 64) {
        float2 r[16];
#pragma unroll
        for (int b = 0; b < 16; b++) r[b] = S[b*64 + tid];
        dif16(r);
#pragma unroll
        for (int p = 0; p < 16; p++) S[p*64 + tid] = r[p];
    }
    __syncthreads();

    int lane = tid & 31;
    int h = brev8(hs);
    const float sc = 1.0f / 32.0f;
#pragma unroll
    for (int it = 0; it < 4; it++) {
        int p = (tid >> 5) + 4*it;
        float2 z0 = S[p*64 + lane];
        float2 z1 = S[p*64 + lane + 32];
        {
            float2 tw = Wang((float)lane, sc);
            float2 a = z0, b = z1;
            z0 = cadd(a, b);
            z1 = cmul(tw, csub(a, b));
        }
#pragma unroll
        for (int m = 16; m >= 1; m >>= 1) {
            float2 tw = Wang((float)((lane & (m-1)) * (32/m)), sc);
            bool hi = (lane & m) != 0;
            float2 o;
            o.x = __shfl_xor_sync(0xffffffffu, z0.x, m);
            o.y = __shfl_xor_sync(0xffffffffu, z0.y, m);
            z0 = hi ? cmul(tw, csub(o, z0)) : cadd(z0, o);
            o.x = __shfl_xor_sync(0xffffffffu, z1.x, m);
            o.y = __shfl_xor_sync(0xffffffffu, z1.y, m);
            z1 = hi ? cmul(tw, csub(o, z1)) : cadd(z1, o);
        }
        int b = brev4(p);
        int c0t = brev6(lane);
        int c1t = brev6(lane + 32);
        out[((size_t)((b << 6) | c0t) * 256 + h) * 256 + 128] = (z0.x + z0.y) * INV_N;
        out[((size_t)((b << 6) | c1t) * 256 + h) * 256 + 128] = (z1.x + z1.y) * INV_N;
    }
}

// ---------------------------------------------------------------------------
extern "C" void kernel_launch(void* const* d_in, const int* in_sizes, int n_in,
                              void* d_out, int out_size) {
    (void)in_sizes; (void)n_in; (void)out_size;
    const float* x = (const float*)d_in[0];
    float* out = (float*)d_out;

    static int smem_set = 0;
    if (!smem_set) {
        cudaFuncSetAttribute(p12_kernel,
                             cudaFuncAttributeMaxDynamicSharedMemorySize,
                             128 * TP * (int)sizeof(unsigned int));
        cudaFuncSetAttribute(p3_kernel,
                             cudaFuncAttributeMaxDynamicSharedMemorySize,
                             1024 * SR * (int)sizeof(float2));
        smem_set = 1;
    }

    p12_kernel<<<1024, 1024, 128 * TP * sizeof(unsigned int)>>>(x);
    p3_kernel<<<4096, 512, 1024 * SR * sizeof(float2)>>>(out);
    p3e_kernel<<<256, 128>>>(out);
}

// round 12
// speedup vs baseline: 1.0301x; 1.0301x over previous
#include <cuda_runtime.h>
#include <cuda_fp16.h>

// out[b,c,h,w] = (Re + Im)( FFT4D(x) ) / 2^26 ; x: [16,64,256,256] f32.
//
// Pipeline:
//  p12: x -> B[ns][bc][w']   (fused real W-FFT (two-for-one) + H-FFT in one
//        130KB smem tile per bc; ns = FFT position, true h = brev8(ns))
//  p3 : B -> out             (16-pt B-FFT + 64-pt C-FFT + Hermitian-mirror
//                             output, fused; w' 0..127)
//  p3e: w'=128 plane -> out column w=128
#define W2 132
__device__ unsigned int g_B[34603008];   // 1024*256*132 half2

#define INV_N (1.0f / 67108864.0f)
#define PI_F 3.14159265358979f

__device__ __forceinline__ float2 cmul(float2 a, float2 b) {
    return make_float2(a.x*b.x - a.y*b.y, a.x*b.y + a.y*b.x);
}
__device__ __forceinline__ float2 cadd(float2 a, float2 b) { return make_float2(a.x+b.x, a.y+b.y); }
__device__ __forceinline__ float2 csub(float2 a, float2 b) { return make_float2(a.x-b.x, a.y-b.y); }
__device__ __forceinline__ float2 Wang(float e, float sc) {   // exp(-i*pi*e*sc), MUFU
    float2 w; __sincosf(-e * sc * PI_F, &w.y, &w.x); return w;
}
__device__ __forceinline__ unsigned int pk(float2 v) {
    __half2 h = __floats2half2_rn(v.x, v.y);
    return *reinterpret_cast<unsigned int*>(&h);
}
__device__ __forceinline__ float2 upk(unsigned int u) {
    __half2 h = *reinterpret_cast<__half2*>(&u);
    return __half22float2(h);
}
__device__ __forceinline__ int brev4(int v) { return (int)(__brev((unsigned)v) >> 28); }
__device__ __forceinline__ int brev6(int v) { return (int)(__brev((unsigned)v) >> 26); }
__device__ __forceinline__ int brev8(int v) { return (int)(__brev((unsigned)v) >> 24); }

// W16^e, e = 0..7
__device__ __constant__ float2 T16C[8] = {
    { 1.00000000f,  0.00000000f}, { 0.92387953f, -0.38268343f},
    { 0.70710678f, -0.70710678f}, { 0.38268343f, -0.92387953f},
    { 0.00000000f, -1.00000000f}, {-0.38268343f, -0.92387953f},
    {-0.70710678f, -0.70710678f}, {-0.92387953f, -0.38268343f}};

// ---------------------------------------------------------------------------
// Per-lane twiddle table for the 256-pt warp FFT: TWS[12][32] float2.
// Entries for lane L: [0..3] W256^(L+32i); [4] W256^(2L); [5] W256^(2L+64);
// [6] W256^(4L); [7..11] cross stages m=16,8,4,2,1: W256^((L&(m-1))*(128/m)).
// ---------------------------------------------------------------------------
__device__ __forceinline__ void fill_tw256(float2* TWS, int tid) {
    if (tid < 32) {
        const float sc = 1.0f / 128.0f;
        int L = tid;
        TWS[0*32+L] = Wang((float)(L      ), sc);
        TWS[1*32+L] = Wang((float)(L +  32), sc);
        TWS[2*32+L] = Wang((float)(L +  64), sc);
        TWS[3*32+L] = Wang((float)(L +  96), sc);
        TWS[4*32+L] = Wang((float)(2*L    ), sc);
        TWS[5*32+L] = Wang((float)(2*L+ 64), sc);
        TWS[6*32+L] = Wang((float)(4*L    ), sc);
        int s = 7;
#pragma unroll
        for (int m = 16; m >= 1; m >>= 1) {
            TWS[s*32+L] = Wang((float)((L & (m-1)) * (128/m)), sc);
            s++;
        }
    }
}

// Warp-resident 256-pt DIF FFT, twiddles from per-lane smem table.
// Input z[i] = x[lane + 32*i] natural order; output pos n holds X[brev8(n)].
__device__ __forceinline__ void fft256_warp(float2 z[8], const float2* twl) {
    // twl = TWS + lane (stride 32 per stage)
#pragma unroll
    for (int i = 0; i < 4; i++) {                       // h = 128
        float2 a = z[i], b = z[i+4];
        z[i]   = cadd(a, b);
        z[i+4] = cmul(twl[i*32], csub(a, b));
    }
    {                                                   // h = 64
        float2 w0 = twl[4*32], w1 = twl[5*32];
        float2 a, b;
        a = z[0]; b = z[2]; z[0] = cadd(a,b); z[2] = cmul(w0, csub(a,b));
        a = z[1]; b = z[3]; z[1] = cadd(a,b); z[3] = cmul(w1, csub(a,b));
        a = z[4]; b = z[6]; z[4] = cadd(a,b); z[6] = cmul(w0, csub(a,b));
        a = z[5]; b = z[7]; z[5] = cadd(a,b); z[7] = cmul(w1, csub(a,b));
    }
    {                                                   // h = 32
        float2 w = twl[6*32];
#pragma unroll
        for (int i = 0; i < 8; i += 2) {
            float2 a = z[i], b = z[i+1];
            z[i]   = cadd(a, b);
            z[i+1] = cmul(w, csub(a, b));
        }
    }
    int s = 7;
    int lane = threadIdx.x & 31;
#pragma unroll
    for (int m = 16; m >= 1; m >>= 1) {                 // cross-lane stages
        float2 w = twl[s*32]; s++;
        bool hi = (lane & m) != 0;
#pragma unroll
        for (int i = 0; i < 8; i++) {
            float2 o;
            o.x = __shfl_xor_sync(0xffffffffu, z[i].x, m);
            o.y = __shfl_xor_sync(0xffffffffu, z[i].y, m);
            if (hi) z[i] = cmul(w, csub(o, z[i]));
            else    z[i] = cadd(z[i], o);
        }
    }
}

// 16-pt DIF; position p holds spectrum index brev4(p).
__device__ __forceinline__ void dif16(float2 r[16]) {
#pragma unroll
    for (int h = 8; h >= 1; h >>= 1) {
#pragma unroll
        for (int base = 0; base < 16; base += 2*h) {
#pragma unroll
            for (int j = 0; j < h; j++) {
                float2 a = r[base+j], b = r[base+j+h];
                r[base+j]   = cadd(a, b);
                r[base+j+h] = cmul(T16C[j * (8/h)], csub(a, b));
            }
        }
    }
}

// Column swizzle for the p12 tile: spreads brev-pattern columns over banks.
#define SWC(c) ((c) ^ (((c) >> 5) & 7))

// ---------------------------------------------------------------------------
// p12: fused W-FFT + H-FFT for one bc plane. 1024 threads.
// Smem: T[128][259] packed half2 (129.5KB) + TWS (3KB).
// ---------------------------------------------------------------------------
#define TP 259
__global__ void __launch_bounds__(1024) p12_kernel(const float* __restrict__ x) {
    extern __shared__ unsigned int T[];   // [128][TP] then TWS
    float2* TWS = (float2*)(T + 128 * TP);
    int tid  = threadIdx.x;
    int lane = tid & 31, wp = tid >> 5;   // 32 warps
    int bc = blockIdx.x;

    fill_tw256(TWS, tid);
    __syncthreads();
    const float2* twl = TWS + lane;

    // W-phase: 128 two-for-one FFTs (pair p = rows 2p,2p+1 packed re/im).
#pragma unroll
    for (int it = 0; it < 4; it++) {
        int p = wp + 32*it;
        const float* r0 = x + ((size_t)bc * 256 + 2*p) * 256;
        float2 z[8];
#pragma unroll
        for (int i = 0; i < 8; i++) {
            int n = lane + 32*i;
            z[i] = make_float2(r0[n], r0[256 + n]);
        }
        fft256_warp(z, twl);
#pragma unroll
        for (int i = 0; i < 8; i++)
            T[p * TP + SWC(lane + 32*i)] = pk(z[i]);
    }
    __syncthreads();

    // H-phase: 129 column tasks over 32 warps (warp 0 also takes task 128).
    for (int it = 0; it < 5; it++) {
        int wq = wp + 32*it;
        if (wq > 128) break;
        int q1 = SWC(brev8(wq));
        int q2 = (wq == 0) ? q1 : SWC(brev8(256 - wq));
        float2 z[8];
#pragma unroll
        for (int i = 0; i < 8; i++) {
            int h  = lane + 32*i;
            int pr = h >> 1;
            float2 Z1 = upk(T[pr * TP + q1]);
            float2 Z2 = upk(T[pr * TP + q2]);
            if (h & 1) z[i] = make_float2(0.5f*(Z1.y + Z2.y), 0.5f*(Z2.x - Z1.x));
            else       z[i] = make_float2(0.5f*(Z1.x + Z2.x), 0.5f*(Z1.y - Z2.y));
        }
        fft256_warp(z, twl);
        int cq2 = (wq == 0) ? 256 : (wq == 128 ? 257 : q2);
#pragma unroll
        for (int i = 0; i < 4; i++)
            T[(lane + 32*i) * TP + q1] = pk(z[i]);
#pragma unroll
        for (int i = 4; i < 8; i++)
            T[(lane + 32*(i-4)) * TP + cq2] = pk(z[i]);
    }
    __syncthreads();

    // Store phase: group g (of 8) handles rows ns = g+8j; coalesced 512B rows.
    int wq = tid & 127;
    int g  = tid >> 7;
    int q1  = SWC(brev8(wq));
    int q2s = (wq == 0) ? 256 : SWC(brev8(256 - wq));
    unsigned int* dB = g_B + bc * (size_t)W2;
#pragma unroll
    for (int j = 0; j < 32; j++) {
        int ns = g + 8*j;
        unsigned int v = (ns < 128) ? T[ns * TP + q1]
                                    : T[(ns - 128) * TP + q2s];
        dB[(size_t)ns * 1024 * W2 + wq] = v;
        if (wq == 0) {   // w'=128 column
            unsigned int v2 = (ns < 128) ? T[ns * TP + SWC(1)]
                                         : T[(ns - 128) * TP + 257];
            dB[(size_t)ns * 1024 * W2 + 128] = v2;
        }
    }
}

// ---------------------------------------------------------------------------
// p3: FUSED (B,C)-FFT + output, w' 0..127. Block = (stored h, 8-w'-chunk).
// 512 threads, S[1024][9] float2 (72KB) + TWS3 (1.5KB) -> 2 CTAs/SM.
// ---------------------------------------------------------------------------
#define SR 9
__global__ void __launch_bounds__(512) p3_kernel(float* __restrict__ out) {
    extern __shared__ float2 S[];   // [1024][SR] then TWS3[6][32]
    float2* TWS3 = S + 1024 * SR;
    int tid = threadIdx.x;
    int ch = blockIdx.x & 15;
    int hs = blockIdx.x >> 4;
    int w0 = ch << 3;
    int w  = tid & 7;
    int c  = tid >> 3;              // 0..63

    if (tid < 32) {                 // 64-pt FFT twiddle table
        const float sc = 1.0f / 32.0f;
        int L = tid;
        TWS3[0*32+L] = Wang((float)L, sc);
        int s = 1;
#pragma unroll
        for (int m = 16; m >= 1; m >>= 1) {
            TWS3[s*32+L] = Wang((float)((L & (m-1)) * (32/m)), sc);
            s++;
        }
    }

    // Phase A: 16-pt b-FFT straight from global (coalesced reads).
    {
        const unsigned int* Bb = g_B + (size_t)hs * 1024 * W2 + w0 + w;
        float2 r[16];
#pragma unroll
        for (int b = 0; b < 16; b++) r[b] = upk(Bb[(size_t)(b*64 + c) * W2]);
        dif16(r);
#pragma unroll
        for (int p = 0; p < 16; p++) S[(p*64 + c)*SR + w] = r[p];
    }
    __syncthreads();

    // Phase B: 64-pt c-FFT; warp p owns rows [p*64, p*64+64), cols w0..w0+7.
    int lane = tid & 31;
    int p    = tid >> 5;            // 0..15
    const float2* tw3 = TWS3 + lane;
    float2 tw32 = tw3[0];
#pragma unroll
    for (int wg = 0; wg < 2; wg++) {
        float2 z0[4], z1[4];
#pragma unroll
        for (int k = 0; k < 4; k++) {
            z0[k] = S[(p*64 + lane)*SR      + wg*4 + k];
            z1[k] = S[(p*64 + lane + 32)*SR + wg*4 + k];
        }
#pragma unroll
        for (int k = 0; k < 4; k++) {   // h = 32 register stage
            float2 a = z0[k], b = z1[k];
            z0[k] = cadd(a, b);
            z1[k] = cmul(tw32, csub(a, b));
        }
        int s = 1;
#pragma unroll
        for (int m = 16; m >= 1; m >>= 1) {
            float2 tw = tw3[s*32]; s++;
            bool hi = (lane & m) != 0;
#pragma unroll
            for (int k = 0; k < 4; k++) {
                float2 o;
                o.x = __shfl_xor_sync(0xffffffffu, z0[k].x, m);
                o.y = __shfl_xor_sync(0xffffffffu, z0[k].y, m);
                z0[k] = hi ? cmul(tw, csub(o, z0[k])) : cadd(z0[k], o);
                o.x = __shfl_xor_sync(0xffffffffu, z1[k].x, m);
                o.y = __shfl_xor_sync(0xffffffffu, z1[k].y, m);
                z1[k] = hi ? cmul(tw, csub(o, z1[k])) : cadd(z1[k], o);
            }
        }
#pragma unroll
        for (int k = 0; k < 4; k++) {
            S[(p*64 + lane)*SR      + wg*4 + k] = z0[k];
            S[(p*64 + lane + 32)*SR + wg*4 + k] = z1[k];
        }
    }
    __syncthreads();

    // Phase C: output. row = c + 64*j -> b = brev4(j), true c = brev6(c).
    int h  = brev8(hs);
    int hm = (256 - h) & 255;
    int wv = w0 + w;
    int ct = brev6(c);
#pragma unroll
    for (int j = 0; j < 16; j++) {
        int row = c + 64*j;
        int b = brev4(j);
        float2 v = S[row*SR + w];
        out[((size_t)((b << 6) | ct) * 256 + h) * 256 + wv] = (v.x + v.y) * INV_N;
        if (wv >= 1) {
            int bcm = (((16 - b) & 15) << 6) | ((64 - ct) & 63);
            out[((size_t)bcm * 256 + hm) * 256 + (256 - wv)] = (v.x - v.y) * INV_N;
        }
    }
}

// p3e: (B,C)-FFT + output for the w'=128 plane (self-mirror column).
__global__ void __launch_bounds__(128) p3e_kernel(float* __restrict__ out) {
    __shared__ float2 S[1024];
    int tid = threadIdx.x;
    int hs = blockIdx.x;

    for (int idx = tid; idx < 1024; idx += 128)
        S[idx] = upk(g_B[((size_t)hs * 1024 + idx) * W2 + 128]);
    __syncthreads();

    if (tid < 64) {
        float2 r[16];
#pragma unroll
        for (int b = 0; b < 16; b++) r[b] = S[b*64 + tid];
        dif16(r);
#pragma unroll
        for (int p = 0; p < 16; p++) S[p*64 + tid] = r[p];
    }
    __syncthreads();

    int lane = tid & 31;
    int h = brev8(hs);
    const float sc = 1.0f / 32.0f;
#pragma unroll
    for (int it = 0; it < 4; it++) {
        int p = (tid >> 5) + 4*it;
        float2 z0 = S[p*64 + lane];
        float2 z1 = S[p*64 + lane + 32];
        {
            float2 tw = Wang((float)lane, sc);
            float2 a = z0, b = z1;
            z0 = cadd(a, b);
            z1 = cmul(tw, csub(a, b));
        }
#pragma unroll
        for (int m = 16; m >= 1; m >>= 1) {
            float2 tw = Wang((float)((lane & (m-1)) * (32/m)), sc);
            bool hi = (lane & m) != 0;
            float2 o;
            o.x = __shfl_xor_sync(0xffffffffu, z0.x, m);
            o.y = __shfl_xor_sync(0xffffffffu, z0.y, m);
            z0 = hi ? cmul(tw, csub(o, z0)) : cadd(z0, o);
            o.x = __shfl_xor_sync(0xffffffffu, z1.x, m);
            o.y = __shfl_xor_sync(0xffffffffu, z1.y, m);
            z1 = hi ? cmul(tw, csub(o, z1)) : cadd(z1, o);
        }
        int b = brev4(p);
        int c0t = brev6(lane);
        int c1t = brev6(lane + 32);
        out[((size_t)((b << 6) | c0t) * 256 + h) * 256 + 128] = (z0.x + z0.y) * INV_N;
        out[((size_t)((b << 6) | c1t) * 256 + h) * 256 + 128] = (z1.x + z1.y) * INV_N;
    }
}

// ---------------------------------------------------------------------------
extern "C" void kernel_launch(void* const* d_in, const int* in_sizes, int n_in,
                              void* d_out, int out_size) {
    (void)in_sizes; (void)n_in; (void)out_size;
    const float* x = (const float*)d_in[0];
    float* out = (float*)d_out;

    const int P12_SMEM = 128 * TP * (int)sizeof(unsigned int) + 12 * 32 * (int)sizeof(float2);
    const int P3_SMEM  = 1024 * SR * (int)sizeof(float2) + 6 * 32 * (int)sizeof(float2);

    static int smem_set = 0;
    if (!smem_set) {
        cudaFuncSetAttribute(p12_kernel,
                             cudaFuncAttributeMaxDynamicSharedMemorySize, P12_SMEM);
        cudaFuncSetAttribute(p3_kernel,
                             cudaFuncAttributeMaxDynamicSharedMemorySize, P3_SMEM);
        smem_set = 1;
    }

    p12_kernel<<<1024, 1024, P12_SMEM>>>(x);
    p3_kernel<<<4096, 512, P3_SMEM>>>(out);
    p3e_kernel<<<256, 128>>>(out);
}